// round 15
// baseline (speedup 1.0000x reference)
#include <cuda_runtime.h>
#include <cuda_fp16.h>
#include <cstdint>

// ---------------- problem constants ----------------
#define HID        256
#define OBS_STRIDE 54
#define SELF_OBS   18
#define NBR        6
#define BATCH_N    131072
#define TILE_B     16                    // batches per CTA iteration
#define NTILES     (BATCH_N / TILE_B)    // 8192
#define THREADS    512                   // 16 warps: warp w owns hidden/output cols [16w, 16w+16)
#define GRID_X     152

// smem: exch[2][6][16][32] uint4 (98304 B) then xs[2][16][42] float (5376 B)
#define EXCH_BYTES (2 * NBR * 16 * 32 * 16)
#define XS_STRIDE  42
#define XS_BYTES   (2 * TILE_B * XS_STRIDE * 4)
#define SMEM_BYTES (EXCH_BYTES + XS_BYTES)

// ==================== helpers ====================
static __device__ __forceinline__ float tanha(float x) {
    float y;
    asm("tanh.approx.f32 %0, %1;" : "=f"(y) : "f"(x));
    return y;
}
static __device__ __forceinline__ uint32_t packh2(float a, float b) {
    __half2 h = __floats2half2_rn(a, b);
    return *reinterpret_cast<uint32_t*>(&h);
}
// D[16x8] += A[16x8] * B[8x8]   (f16 in, f32 accum)
static __device__ __forceinline__ void mma_k8(float& d0, float& d1, float& d2, float& d3,
                                              uint32_t a0, uint32_t a1, uint32_t b0) {
    asm volatile("mma.sync.aligned.m16n8k8.row.col.f32.f16.f16.f32 "
                 "{%0,%1,%2,%3}, {%4,%5}, {%6}, {%0,%1,%2,%3};"
                 : "+f"(d0), "+f"(d1), "+f"(d2), "+f"(d3)
                 : "r"(a0), "r"(a1), "r"(b0));
}
// D[16x8] += A[16x16] * B[16x8]
static __device__ __forceinline__ void mma_k16(float* d,
                                               uint32_t a0, uint32_t a1, uint32_t a2, uint32_t a3,
                                               uint32_t b0, uint32_t b1) {
    asm volatile("mma.sync.aligned.m16n8k16.row.col.f32.f16.f16.f32 "
                 "{%0,%1,%2,%3}, {%4,%5,%6,%7}, {%8,%9}, {%0,%1,%2,%3};"
                 : "+f"(d[0]), "+f"(d[1]), "+f"(d[2]), "+f"(d[3])
                 : "r"(a0), "r"(a1), "r"(a2), "r"(a3), "r"(b0), "r"(b1));
}

// ==================== kernel ====================
__global__ void __launch_bounds__(THREADS, 1)
deepsets_kernel(const float* __restrict__ obs,
                const float* __restrict__ W1,
                const float* __restrict__ b1,
                const float* __restrict__ W2,
                const float* __restrict__ b2,
                float* __restrict__ out)
{
    extern __shared__ char smem[];
    // A-fragment exchange: [buf][nb][k-chunk][lane]; chunk c produced by warp c.
    uint4* exch = reinterpret_cast<uint4*>(smem);
    // staged neighbor-obs: xs[p][row][42], rows padded for conflict-free strided reads
    float* xsf = reinterpret_cast<float*>(smem + EXCH_BYTES);

    const int tid  = threadIdx.x;
    const int w    = tid >> 5;      // warp id = 16-col hidden/output n-slice
    const int lane = tid & 31;
    const int gid  = lane >> 4 ? 0 : 0, g2 = 0; (void)g2;  // (placeholder removed below)
    const int grp  = lane >> 2;     // fragment row group (0..7)
    const int tig  = lane & 3;      // thread-in-group
    const int n0   = w * 16;
    const int slot = w >> 2;        // 4-way phase rotation; each SMSP (w%4) gets one of each

    // ---- resident W1 B-fragments + bias fragments ----
    uint32_t w1b[2];
    float2 b1v[2], b2v[2];
    #pragma unroll
    for (int j = 0; j < 2; j++) {
        int tt = 2 * w + j;                 // global hidden n8-tile
        int n  = tt * 8 + grp;
        int c  = tt * 8 + 2 * tig;
        w1b[j] = (tig < 3) ? packh2(W1[2 * tig * HID + n], W1[(2 * tig + 1) * HID + n]) : 0u;
        b1v[j] = make_float2(b1[c], b1[c + 1]);
        b2v[j] = make_float2(b2[c], b2[c + 1]);
    }

    // ---- resident W2 B-fragments: warp w holds W2[:, n0..n0+15] (64 regs) ----
    uint32_t blo[16][2], bhi[16][2];
    #pragma unroll
    for (int c = 0; c < 16; c++) {
        #pragma unroll
        for (int t = 0; t < 2; t++) {
            int n = n0 + t * 8 + grp;
            int k = c * 16 + 2 * tig;
            blo[c][t] = packh2(W2[k * HID + n],       W2[(k + 1) * HID + n]);
            bhi[c][t] = packh2(W2[(k + 8) * HID + n], W2[(k + 9) * HID + n]);
        }
    }

    const float inv6 = 1.0f / 6.0f;

    // stage the 16x36 neighbor-obs block of tile at batch base b0 into xs[p] (coalesced)
    auto xstage = [&](long b0, int p) {
        for (int i = tid; i < TILE_B * 18; i += THREADS) {
            int r = i / 18, c2 = i % 18;
            float2 v = *reinterpret_cast<const float2*>(&obs[(b0 + r) * OBS_STRIDE + SELF_OBS + 2 * c2]);
            *reinterpret_cast<float2*>(&xsf[(p * TILE_B + r) * XS_STRIDE + 2 * c2]) = v;
        }
    };

    // P: layer-1 for neighbor nb of the tile staged in xs[p] -> exch[buf] chunk w
    auto layer1 = [&](int nb, int p, int buf) {
        uint32_t xa0 = 0u, xa1 = 0u;
        if (tig < 3) {
            const float* q = &xsf[(p * TILE_B + grp) * XS_STRIDE + nb * 6 + 2 * tig];
            float2 v0 = *reinterpret_cast<const float2*>(q);
            float2 v1 = *reinterpret_cast<const float2*>(q + 8 * XS_STRIDE);
            xa0 = packh2(v0.x, v0.y);
            xa1 = packh2(v1.x, v1.y);
        }
        uint4 pk;
        uint32_t* pkr = reinterpret_cast<uint32_t*>(&pk);
        #pragma unroll
        for (int j = 0; j < 2; j++) {
            float d0 = 0.f, d1 = 0.f, d2 = 0.f, d3 = 0.f;
            mma_k8(d0, d1, d2, d3, xa0, xa1, w1b[j]);
            pkr[j * 2 + 0] = packh2(tanha(d0 + b1v[j].x), tanha(d1 + b1v[j].y));
            pkr[j * 2 + 1] = packh2(tanha(d2 + b1v[j].x), tanha(d3 + b1v[j].y));
        }
        exch[((buf * NBR + nb) * 16 + w) * 32 + lane] = pk;
    };

    // ---- prologue: stage x(T0) and x(T1); build A(T0) ----
    {
        long t0 = (long)blockIdx.x;
        xstage(t0 * TILE_B, 0);
        if (t0 + GRID_X < NTILES) xstage((t0 + GRID_X) * TILE_B, 1);
        __syncthreads();
        #pragma unroll
        for (int nb = 0; nb < NBR; nb++) layer1(nb, 0, 0);
    }
    __syncthreads();

    int buf = 0;   // this tile consumes exch[buf]; layer1(next) reads xs[buf^1]
    for (int tile = blockIdx.x; tile < NTILES; tile += gridDim.x) {
        const long b0     = (long)tile * TILE_B;
        const bool has_nx = (tile + gridDim.x < NTILES);
        const bool has_n2 = (tile + 2 * gridDim.x < NTILES);

        if (has_n2) xstage((long)(tile + 2 * gridDim.x) * TILE_B, buf);

        float acc[2][4];
        #pragma unroll
        for (int t = 0; t < 2; t++)
            #pragma unroll
            for (int i = 0; i < 4; i++) acc[t][i] = 0.0f;

        // C: HMMA burst over exch[buf][nb] into D
        auto burstD = [&](int nb, float D[2][4]) {
            #pragma unroll
            for (int t = 0; t < 2; t++)
                #pragma unroll
                for (int i = 0; i < 4; i++) D[t][i] = 0.0f;
            const uint4* ap = &exch[((buf * NBR + nb) * 16) * 32 + lane];
            #pragma unroll
            for (int c = 0; c < 16; c++) {
                uint4 a = ap[c * 32];
                mma_k16(D[0], a.x, a.y, a.z, a.w, blo[c][0], bhi[c][0]);
                mma_k16(D[1], a.x, a.y, a.z, a.w, blo[c][1], bhi[c][1]);
            }
        };
        // E: epilogue acc += tanh(D + b2)
        auto epi = [&](const float D[2][4]) {
            #pragma unroll
            for (int t = 0; t < 2; t++) {
                acc[t][0] += tanha(D[t][0] + b2v[t].x);
                acc[t][1] += tanha(D[t][1] + b2v[t].y);
                acc[t][2] += tanha(D[t][2] + b2v[t].x);
                acc[t][3] += tanha(D[t][3] + b2v[t].y);
            }
        };

        // 4-way phase rotation: blocks P (layer1, writes exch[buf^1]),
        // C (burst, reads exch[buf]), E (epilogue of a completed D) are mutually
        // independent -> any per-warp order is legal. Each SMSP holds one warp
        // of each rotation, desynchronizing tensor-pipe demand.
        if (slot == 0) {            // P, C, E
            #pragma unroll
            for (int nb = 0; nb < NBR; nb++) {
                if (has_nx) layer1(nb, buf ^ 1, buf ^ 1);
                float D[2][4];
                burstD(nb, D);
                epi(D);
            }
        } else if (slot == 1) {     // C, E, P
            #pragma unroll
            for (int nb = 0; nb < NBR; nb++) {
                float D[2][4];
                burstD(nb, D);
                epi(D);
                if (has_nx) layer1(nb, buf ^ 1, buf ^ 1);
            }
        } else if (slot == 2) {     // E(prev), P, C   (deferred epilogue)
            float Dp[2][4];
            #pragma unroll
            for (int nb = 0; nb < NBR; nb++) {
                if (nb > 0) epi(Dp);
                if (has_nx) layer1(nb, buf ^ 1, buf ^ 1);
                burstD(nb, Dp);
            }
            epi(Dp);
        } else {                    // C, P, E
            #pragma unroll
            for (int nb = 0; nb < NBR; nb++) {
                float D[2][4];
                burstD(nb, D);
                if (has_nx) layer1(nb, buf ^ 1, buf ^ 1);
                epi(D);
            }
        }

        // ---- mean over neighbors, write out ----
        #pragma unroll
        for (int t = 0; t < 2; t++) {
            int col = n0 + t * 8 + 2 * tig;
            float2 v0 = make_float2(acc[t][0] * inv6, acc[t][1] * inv6);
            float2 v1 = make_float2(acc[t][2] * inv6, acc[t][3] * inv6);
            *reinterpret_cast<float2*>(&out[(b0 + grp)     * HID + col]) = v0;
            *reinterpret_cast<float2*>(&out[(b0 + grp + 8) * HID + col]) = v1;
        }

        __syncthreads();  // exch[buf] reads done before rewrite; exch[buf^1] & xs[buf]
                          // writes visible before next tile's reads
        buf ^= 1;
    }
}

// ==================== launch ====================
extern "C" void kernel_launch(void* const* d_in, const int* in_sizes, int n_in,
                              void* d_out, int out_size) {
    // inputs: self_obs(131072*18), obs(131072*54), W1(6*256), b1(256), W2(256*256), b2(256)
    const float* obs = nullptr;
    const float* W1  = nullptr;
    const float* b1  = nullptr;
    const float* W2  = nullptr;
    const float* b2  = nullptr;
    for (int i = 0; i < n_in; i++) {
        int sz = in_sizes[i];
        if (sz == BATCH_N * OBS_STRIDE)  obs = (const float*)d_in[i];
        else if (sz == 6 * HID)          W1  = (const float*)d_in[i];
        else if (sz == HID * HID)        W2  = (const float*)d_in[i];
        else if (sz == HID) {
            if (!b1) b1 = (const float*)d_in[i];
            else if (!b2) b2 = (const float*)d_in[i];
        }
    }
    float* out = (float*)d_out;

    cudaFuncSetAttribute(deepsets_kernel,
                         cudaFuncAttributeMaxDynamicSharedMemorySize, SMEM_BYTES);
    deepsets_kernel<<<GRID_X, THREADS, SMEM_BYTES>>>(obs, W1, b1, W2, b2, out);
}

// round 16
// speedup vs baseline: 1.5637x; 1.5637x over previous
#include <cuda_runtime.h>
#include <cuda_fp16.h>
#include <cstdint>

// ---------------- problem constants ----------------
#define HID        256
#define OBS_STRIDE 54
#define SELF_OBS   18
#define NBR        6
#define BATCH_N    131072
#define TILE_B     16                    // batches per CTA iteration
#define NTILES     (BATCH_N / TILE_B)    // 8192
#define THREADS    512                   // 16 warps: warp w owns hidden/output cols [16w, 16w+16)
#define GRID_X     152

// smem: exch[2][6][16][32] uint4 (98304 B) then xs[2][16][42] float (5376 B)
#define EXCH_BYTES (2 * NBR * 16 * 32 * 16)
#define XS_STRIDE  42
#define XS_BYTES   (2 * TILE_B * XS_STRIDE * 4)
#define SMEM_BYTES (EXCH_BYTES + XS_BYTES)

// ==================== helpers ====================
static __device__ __forceinline__ float tanha(float x) {
    float y;
    asm("tanh.approx.f32 %0, %1;" : "=f"(y) : "f"(x));
    return y;
}
static __device__ __forceinline__ uint32_t packh2(float a, float b) {
    __half2 h = __floats2half2_rn(a, b);
    return *reinterpret_cast<uint32_t*>(&h);
}
// D[16x8] += A[16x8] * B[8x8]   (f16 in, f32 accum)
static __device__ __forceinline__ void mma_k8(float& d0, float& d1, float& d2, float& d3,
                                              uint32_t a0, uint32_t a1, uint32_t b0) {
    asm volatile("mma.sync.aligned.m16n8k8.row.col.f32.f16.f16.f32 "
                 "{%0,%1,%2,%3}, {%4,%5}, {%6}, {%0,%1,%2,%3};"
                 : "+f"(d0), "+f"(d1), "+f"(d2), "+f"(d3)
                 : "r"(a0), "r"(a1), "r"(b0));
}
// D[16x8] += A[16x16] * B[16x8]
static __device__ __forceinline__ void mma_k16(float* d,
                                               uint32_t a0, uint32_t a1, uint32_t a2, uint32_t a3,
                                               uint32_t b0, uint32_t b1) {
    asm volatile("mma.sync.aligned.m16n8k16.row.col.f32.f16.f16.f32 "
                 "{%0,%1,%2,%3}, {%4,%5,%6,%7}, {%8,%9}, {%0,%1,%2,%3};"
                 : "+f"(d[0]), "+f"(d[1]), "+f"(d[2]), "+f"(d[3])
                 : "r"(a0), "r"(a1), "r"(a2), "r"(a3), "r"(b0), "r"(b1));
}

// ==================== kernel ====================
__global__ void __launch_bounds__(THREADS, 1)
deepsets_kernel(const float* __restrict__ obs,
                const float* __restrict__ W1,
                const float* __restrict__ b1,
                const float* __restrict__ W2,
                const float* __restrict__ b2,
                float* __restrict__ out)
{
    extern __shared__ char smem[];
    // A-fragment exchange: [buf][nb][k-chunk][lane]; chunk c produced by warp c.
    uint4* exch = reinterpret_cast<uint4*>(smem);
    // staged neighbor-obs: xs[p][row][42], rows padded for conflict-free strided reads
    float* xsf = reinterpret_cast<float*>(smem + EXCH_BYTES);

    const int tid  = threadIdx.x;
    const int w    = tid >> 5;      // warp id = 16-col hidden/output n-slice
    const int lane = tid & 31;
    const int gid  = lane >> 2;     // fragment row group (0..7)
    const int tig  = lane & 3;      // thread-in-group
    const int n0   = w * 16;
    const bool wodd = (w & 1);      // phase-stagger parity

    // ---- resident W1 B-fragments + bias fragments ----
    uint32_t w1b[2];
    float2 b1v[2], b2v[2];
    #pragma unroll
    for (int j = 0; j < 2; j++) {
        int tt = 2 * w + j;                 // global hidden n8-tile
        int n  = tt * 8 + gid;
        int c  = tt * 8 + 2 * tig;
        w1b[j] = (tig < 3) ? packh2(W1[2 * tig * HID + n], W1[(2 * tig + 1) * HID + n]) : 0u;
        b1v[j] = make_float2(b1[c], b1[c + 1]);
        b2v[j] = make_float2(b2[c], b2[c + 1]);
    }

    // ---- resident W2 B-fragments: warp w holds W2[:, n0..n0+15] (64 regs) ----
    uint32_t blo[16][2], bhi[16][2];
    #pragma unroll
    for (int c = 0; c < 16; c++) {
        #pragma unroll
        for (int t = 0; t < 2; t++) {
            int n = n0 + t * 8 + gid;
            int k = c * 16 + 2 * tig;
            blo[c][t] = packh2(W2[k * HID + n],       W2[(k + 1) * HID + n]);
            bhi[c][t] = packh2(W2[(k + 8) * HID + n], W2[(k + 9) * HID + n]);
        }
    }

    const float inv6 = 1.0f / 6.0f;

    // stage the 16x36 neighbor-obs block of tile at batch base b0 into xs[p] (coalesced)
    auto xstage = [&](long b0, int p) {
        for (int i = tid; i < TILE_B * 18; i += THREADS) {
            int r = i / 18, c2 = i % 18;
            float2 v = *reinterpret_cast<const float2*>(&obs[(b0 + r) * OBS_STRIDE + SELF_OBS + 2 * c2]);
            *reinterpret_cast<float2*>(&xsf[(p * TILE_B + r) * XS_STRIDE + 2 * c2]) = v;
        }
    };

    // layer-1 for neighbor nb of the tile staged in xs[p] -> exch[buf] chunk w
    auto layer1 = [&](int nb, int p, int buf) {
        uint32_t xa0 = 0u, xa1 = 0u;
        if (tig < 3) {
            const float* q = &xsf[(p * TILE_B + gid) * XS_STRIDE + nb * 6 + 2 * tig];
            float2 v0 = *reinterpret_cast<const float2*>(q);
            float2 v1 = *reinterpret_cast<const float2*>(q + 8 * XS_STRIDE);
            xa0 = packh2(v0.x, v0.y);
            xa1 = packh2(v1.x, v1.y);
        }
        uint4 pk;
        uint32_t* pkr = reinterpret_cast<uint32_t*>(&pk);
        #pragma unroll
        for (int j = 0; j < 2; j++) {
            float d0 = 0.f, d1 = 0.f, d2 = 0.f, d3 = 0.f;
            mma_k8(d0, d1, d2, d3, xa0, xa1, w1b[j]);
            pkr[j * 2 + 0] = packh2(tanha(d0 + b1v[j].x), tanha(d1 + b1v[j].y));
            pkr[j * 2 + 1] = packh2(tanha(d2 + b1v[j].x), tanha(d3 + b1v[j].y));
        }
        exch[((buf * NBR + nb) * 16 + w) * 32 + lane] = pk;
    };

    // ---- prologue: stage x(T0) and x(T1); build A(T0) ----
    {
        long t0 = (long)blockIdx.x;
        xstage(t0 * TILE_B, 0);
        if (t0 + GRID_X < NTILES) xstage((t0 + GRID_X) * TILE_B, 1);
        __syncthreads();
        #pragma unroll
        for (int nb = 0; nb < NBR; nb++) layer1(nb, 0, 0);
    }
    __syncthreads();

    int buf = 0;   // this tile consumes exch[buf]; layer1(next) reads xs[buf^1]
    for (int tile = blockIdx.x; tile < NTILES; tile += gridDim.x) {
        const long b0     = (long)tile * TILE_B;
        const bool has_nx = (tile + gridDim.x < NTILES);
        const bool has_n2 = (tile + 2 * gridDim.x < NTILES);

        // stage x(tile+2) into xs[buf] (its old contents were last read during the
        // previous tile's layer1 — separated by the loop barrier).
        if (has_n2) xstage((long)(tile + 2 * gridDim.x) * TILE_B, buf);

        float acc[2][4];
        #pragma unroll
        for (int t = 0; t < 2; t++)
            #pragma unroll
            for (int i = 0; i < 4; i++) acc[t][i] = 0.0f;

        // burst: depth-2 software-pipelined LDS -> HMMA over exch[buf][nb] + epilogue.
        // Chunk c+2's load issues before chunk c's HMMAs: ~30-cyc LDS latency is
        // covered by two iterations of tensor issue; only 2 uint4 (8 regs) in flight.
        auto burst = [&](int nb) {
            float D[2][4];
            #pragma unroll
            for (int t = 0; t < 2; t++)
                #pragma unroll
                for (int i = 0; i < 4; i++) D[t][i] = 0.0f;

            const uint4* ap = &exch[((buf * NBR + nb) * 16) * 32 + lane];
            uint4 a0 = ap[0];
            uint4 a1 = ap[32];
            #pragma unroll
            for (int c = 0; c < 16; c++) {
                uint4 an;
                if (c < 14) an = ap[(c + 2) * 32];   // prefetch 2 chunks ahead
                mma_k16(D[0], a0.x, a0.y, a0.z, a0.w, blo[c][0], bhi[c][0]);
                mma_k16(D[1], a0.x, a0.y, a0.z, a0.w, blo[c][1], bhi[c][1]);
                a0 = a1;
                if (c < 14) a1 = an;
            }

            // immediate epilogue (MUFUs overlap other warps' tensor via stagger)
            #pragma unroll
            for (int t = 0; t < 2; t++) {
                acc[t][0] += tanha(D[t][0] + b2v[t].x);
                acc[t][1] += tanha(D[t][1] + b2v[t].y);
                acc[t][2] += tanha(D[t][2] + b2v[t].x);
                acc[t][3] += tanha(D[t][3] + b2v[t].y);
            }
        };

        // Phase-staggered interleave: even warps (layer1 -> burst), odd warps
        // (burst -> layer1). Legal: burst(nb) reads exch[buf] (written last tile),
        // layer1(nb) writes exch[buf^1].
        #pragma unroll
        for (int nb = 0; nb < NBR; nb++) {
            if (wodd) {
                burst(nb);
                if (has_nx) layer1(nb, buf ^ 1, buf ^ 1);
            } else {
                if (has_nx) layer1(nb, buf ^ 1, buf ^ 1);
                burst(nb);
            }
        }

        // ---- mean over neighbors, write out ----
        #pragma unroll
        for (int t = 0; t < 2; t++) {
            int col = n0 + t * 8 + 2 * tig;
            float2 v0 = make_float2(acc[t][0] * inv6, acc[t][1] * inv6);
            float2 v1 = make_float2(acc[t][2] * inv6, acc[t][3] * inv6);
            *reinterpret_cast<float2*>(&out[(b0 + gid)     * HID + col]) = v0;
            *reinterpret_cast<float2*>(&out[(b0 + gid + 8) * HID + col]) = v1;
        }

        __syncthreads();  // exch[buf] reads done before rewrite; exch[buf^1] & xs[buf]
                          // writes visible before next tile's reads
        buf ^= 1;
    }
}

// ==================== launch ====================
extern "C" void kernel_launch(void* const* d_in, const int* in_sizes, int n_in,
                              void* d_out, int out_size) {
    // inputs: self_obs(131072*18), obs(131072*54), W1(6*256), b1(256), W2(256*256), b2(256)
    const float* obs = nullptr;
    const float* W1  = nullptr;
    const float* b1  = nullptr;
    const float* W2  = nullptr;
    const float* b2  = nullptr;
    for (int i = 0; i < n_in; i++) {
        int sz = in_sizes[i];
        if (sz == BATCH_N * OBS_STRIDE)  obs = (const float*)d_in[i];
        else if (sz == 6 * HID)          W1  = (const float*)d_in[i];
        else if (sz == HID * HID)        W2  = (const float*)d_in[i];
        else if (sz == HID) {
            if (!b1) b1 = (const float*)d_in[i];
            else if (!b2) b2 = (const float*)d_in[i];
        }
    }
    float* out = (float*)d_out;

    cudaFuncSetAttribute(deepsets_kernel,
                         cudaFuncAttributeMaxDynamicSharedMemorySize, SMEM_BYTES);
    deepsets_kernel<<<GRID_X, THREADS, SMEM_BYTES>>>(obs, W1, b1, W2, b2, out);
}